// round 5
// baseline (speedup 1.0000x reference)
#include <cuda_runtime.h>
#include <cuda_bf16.h>
#include <stdint.h>

// Shapes (fixed):
//   updates: (8,128,128,256) float32 -> 33,554,432 elems
//   mask:    same shape int32 in [0, 16,777,216)
//   output:  (8,256,256,256) float32 -> 134,217,728 elems (512 MB)
// out[mask[i] + (i>>22)<<22] += updates[i]; rest zeros.
// Scatter region = [0, 46,137,344) (184 MB); tail (352 MB) never touched.
//
// Atomic LTS slots are the wall (~64 scalar REDs/cyc). Composition:
//   memset(W0, 92 MB)
//   pass0: atomics into W0  + zero W1 (plain stores -> dirty in L2 for pass1)
//                           + zero tail half A (__stwt, no L2 allocation)
//   pass1: atomics into W1  + zero tail half B (__stwt)

#define N_ELEMS      33554432u
#define N_VEC4       (N_ELEMS / 4u)             // 8,388,608 threads per pass
#define BATCH_V4_SH  20
#define BATCH_OFF_SH 22
#define SCATTER_END  46137344u
#define W_SPLIT      23068672u                  // W0=[0,W_SPLIT) W1=[W_SPLIT,END)
#define W_SPLIT_V4   (W_SPLIT / 4u)             // 5,767,168
#define W1_V4        ((SCATTER_END - W_SPLIT) / 4u)   // 5,767,168
#define OUT_ELEMS    134217728u
#define TAIL_START_V4 (SCATTER_END / 4u)        // 11,534,336
#define TAIL_V4      ((OUT_ELEMS - SCATTER_END) / 4u) // 22,020,096
#define TAIL_HALF_V4 (TAIL_V4 / 2u)             // 11,010,048

__global__ __launch_bounds__(256, 8)
void scatter_pass_kernel(const float4* __restrict__ upd4,
                         const int4*  __restrict__ msk4,
                         float* __restrict__ out,
                         unsigned int wlo, unsigned int whi,
                         unsigned int zero_w1,        // 1 on pass 0
                         unsigned int tail_base_v4)   // tail half start (v4)
{
    unsigned int i = blockIdx.x * 256u + threadIdx.x;   // [0, N_VEC4)

    float4 u = __ldcs(upd4 + i);
    int4   m = __ldcs(msk4 + i);

    const float4 z = make_float4(0.f, 0.f, 0.f, 0.f);
    float4* out4 = (float4*)out;

    // Pass 0 only: zero W1 with plain stores so it's L2-dirty for pass 1.
    if (zero_w1 && i < W1_V4)
        out4[W_SPLIT_V4 + i] = z;

    // Zero this pass's half of the dead tail. Write-through, no L2 allocation
    // (protects the atomic window's L2 residency).
    #pragma unroll
    for (unsigned int k = 0; k < 2; k++) {
        unsigned int t = i + k * N_VEC4;
        if (t < TAIL_HALF_V4)
            __stwt(out4 + TAIL_START_V4 + tail_base_v4 + t, z);
    }

    // Scatter-add into the L2-resident window only.
    unsigned int base = (i >> BATCH_V4_SH) << BATCH_OFF_SH;
    unsigned int ix = base + (unsigned int)m.x;
    unsigned int iy = base + (unsigned int)m.y;
    unsigned int iz = base + (unsigned int)m.z;
    unsigned int iw = base + (unsigned int)m.w;

    if (ix >= wlo && ix < whi) atomicAdd(out + ix, u.x);
    if (iy >= wlo && iy < whi) atomicAdd(out + iy, u.y);
    if (iz >= wlo && iz < whi) atomicAdd(out + iz, u.z);
    if (iw >= wlo && iw < whi) atomicAdd(out + iw, u.w);
}

extern "C" void kernel_launch(void* const* d_in, const int* in_sizes, int n_in,
                              void* d_out, int out_size)
{
    const float4* upd4 = (const float4*)d_in[0];
    const int4*   msk4 = (const int4*)d_in[1];
    float* out = (float*)d_out;

    const int threads = 256;
    const int blocks  = (int)(N_VEC4 / threads);   // 32768

    // Zero window 0 (92 MB) — the only separate fill step.
    cudaMemsetAsync(out, 0, (size_t)W_SPLIT * sizeof(float), 0);

    // Pass 0: atomics in W0, zero W1, zero tail half A.
    scatter_pass_kernel<<<blocks, threads>>>(upd4, msk4, out,
                                             0u, W_SPLIT, 1u, 0u);
    // Pass 1: atomics in W1 (L2-dirty from pass 0), zero tail half B.
    scatter_pass_kernel<<<blocks, threads>>>(upd4, msk4, out,
                                             W_SPLIT, SCATTER_END, 0u,
                                             TAIL_HALF_V4);
}

// round 6
// speedup vs baseline: 1.1590x; 1.1590x over previous
#include <cuda_runtime.h>
#include <cuda_bf16.h>
#include <stdint.h>

// Shapes (fixed):
//   updates: (8,128,128,256) float32 -> 33,554,432 elems
//   mask:    same shape int32 in [0, 16,777,216)
//   output:  (8,256,256,256) float32 -> 134,217,728 elems (512 MB)
// out[mask[i] + (i>>22)<<22] += updates[i]; rest zeros.
// Scatter region = [0, 46,137,344) (184 MB); tail (352 MB) never touched.
//
// R4 structure (best) + the dead-tail zero-fill moved to a FORKED capture
// branch so its ~50 us runs concurrently with the LTS-bound scatter passes
// (DRAM has >50% headroom there; __stwt avoids polluting the L2 window).

#define N_ELEMS      33554432u
#define N_VEC4       (N_ELEMS / 4u)             // 8,388,608
#define BATCH_V4_SH  20
#define BATCH_OFF_SH 22
#define SCATTER_END  46137344u
#define W_SPLIT      23068672u                  // W0=[0,W_SPLIT) W1=[W_SPLIT,END)
#define OUT_ELEMS    134217728u
#define TAIL_START_V4 (SCATTER_END / 4u)        // 11,534,336
#define TAIL_V4      ((OUT_ELEMS - SCATTER_END) / 4u)  // 22,020,096

__global__ __launch_bounds__(256, 8)
void scatter_pass_kernel(const float4* __restrict__ upd4,
                         const int4*  __restrict__ msk4,
                         float* __restrict__ out,
                         unsigned int wlo, unsigned int whi)
{
    unsigned int i = blockIdx.x * 256u + threadIdx.x;   // [0, N_VEC4)

    float4 u = __ldcs(upd4 + i);
    int4   m = __ldcs(msk4 + i);

    unsigned int base = (i >> BATCH_V4_SH) << BATCH_OFF_SH;
    unsigned int ix = base + (unsigned int)m.x;
    unsigned int iy = base + (unsigned int)m.y;
    unsigned int iz = base + (unsigned int)m.z;
    unsigned int iw = base + (unsigned int)m.w;

    // Atomics only into the current L2-resident window.
    if (ix >= wlo && ix < whi) atomicAdd(out + ix, u.x);
    if (iy >= wlo && iy < whi) atomicAdd(out + iy, u.y);
    if (iz >= wlo && iz < whi) atomicAdd(out + iz, u.z);
    if (iw >= wlo && iw < whi) atomicAdd(out + iw, u.w);
}

__global__ __launch_bounds__(256, 8)
void zero_tail_kernel(float4* __restrict__ out4)
{
    unsigned int i = blockIdx.x * 256u + threadIdx.x;
    const float4 z = make_float4(0.f, 0.f, 0.f, 0.f);
    // Write-through, no L2 allocation: never evicts the atomic window.
    #pragma unroll
    for (unsigned int k = 0; k < 4; k++) {
        unsigned int t = i + k * (TAIL_V4 / 4u);
        __stwt(out4 + TAIL_START_V4 + t, z);
    }
}

extern "C" void kernel_launch(void* const* d_in, const int* in_sizes, int n_in,
                              void* d_out, int out_size)
{
    const float4* upd4 = (const float4*)d_in[0];
    const int4*   msk4 = (const int4*)d_in[1];
    float* out = (float*)d_out;

    // One-time side stream + events (no device memory involved).
    static cudaStream_t side = nullptr;
    static cudaEvent_t ev_fork = nullptr, ev_join = nullptr;
    if (side == nullptr) {
        cudaStreamCreateWithFlags(&side, cudaStreamNonBlocking);
        cudaEventCreateWithFlags(&ev_fork, cudaEventDisableTiming);
        cudaEventCreateWithFlags(&ev_join, cudaEventDisableTiming);
    }

    const int threads = 256;
    const int blocks  = (int)(N_VEC4 / threads);        // 32768
    const int tail_blocks = (int)(TAIL_V4 / 4u / threads); // 21504

    // Fork: tail zero-fill runs concurrently with the scatter chain.
    cudaEventRecord(ev_fork, 0);
    cudaStreamWaitEvent(side, ev_fork, 0);
    zero_tail_kernel<<<tail_blocks, threads, 0, side>>>((float4*)d_out);
    cudaEventRecord(ev_join, side);

    // Serial scatter chain on the capture stream.
    cudaMemsetAsync(out, 0, (size_t)W_SPLIT * sizeof(float), 0);
    scatter_pass_kernel<<<blocks, threads>>>(upd4, msk4, out, 0u, W_SPLIT);
    cudaMemsetAsync(out + W_SPLIT, 0,
                    (size_t)(SCATTER_END - W_SPLIT) * sizeof(float), 0);
    scatter_pass_kernel<<<blocks, threads>>>(upd4, msk4, out,
                                             W_SPLIT, SCATTER_END);

    // Join: output is complete only after both branches finish.
    cudaStreamWaitEvent(0, ev_join, 0);
}